// round 13
// baseline (speedup 1.0000x reference)
#include <cuda_runtime.h>
#include <cuda_bf16.h>
#include <cstdint>

#define BB 256
#define TT 1024
#define WW 512
#define UU 512
#define PP 16
#define TP (TT - PP + 1)
#define MTOT (BB * TP)

__device__ __align__(16) __nv_bfloat16 g_Ah[(size_t)MTOT * WW];
__device__ __align__(16) __nv_bfloat16 g_Al[(size_t)MTOT * WW];
__device__ __align__(16) __nv_bfloat16 g_Bh[WW * UU];    // K^T hi [n][k]
__device__ __align__(16) __nv_bfloat16 g_Bl[WW * UU];    // K^T lo [n][k]
__device__ __align__(16) __nv_bfloat16 g_Rth[UU * UU];   // R^T hi [n][k]
__device__ __align__(16) __nv_bfloat16 g_Rtl[UU * UU];   // R^T lo [n][k]
__device__ __align__(16) __nv_bfloat16 g_sbf[2][2][BB * UU]; // [parity][hi/lo]
__device__ unsigned g_cnt[16 * 32];   // per-group step counter, 128B padded

typedef unsigned long long u64;
__device__ __forceinline__ unsigned ld_acq(const unsigned* p) {
    unsigned v;
    asm volatile("ld.global.acquire.gpu.u32 %0, [%1];" : "=r"(v) : "l"(p) : "memory");
    return v;
}
__device__ __forceinline__ void red_rel(unsigned* p) {
    asm volatile("red.release.gpu.global.add.u32 [%0], 1;" :: "l"(p) : "memory");
}
__device__ __forceinline__ uint32_t smem_u32(const void* p) {
    uint32_t a;
    asm("{ .reg .u64 t; cvta.to.shared.u64 t, %1; cvt.u32.u64 %0, t; }" : "=r"(a) : "l"(p));
    return a;
}
__device__ __forceinline__ void cpa16(uint32_t s, const void* g) {
    asm volatile("cp.async.cg.shared.global [%0], [%1], 16;" :: "r"(s), "l"(g) : "memory");
}
#define CP_COMMIT() asm volatile("cp.async.commit_group;" ::: "memory")
#define CP_WAIT(n)  asm volatile("cp.async.wait_group %0;" :: "n"(n) : "memory")
#define SWZ(x) ((x) ^ (((x) >> 3) & 0x70))
#define LDSM4(r0, r1, r2, r3, a) \
    asm volatile("ldmatrix.sync.aligned.m8n8.x4.shared.b16 {%0,%1,%2,%3}, [%4];" \
                 : "=r"(r0), "=r"(r1), "=r"(r2), "=r"(r3) : "r"(a))
__device__ __forceinline__ void mma_bf16(float* c, const uint32_t* a, const uint32_t* b) {
    asm volatile(
        "mma.sync.aligned.m16n8k16.row.col.f32.bf16.bf16.f32 "
        "{%0,%1,%2,%3}, {%4,%5,%6,%7}, {%8,%9}, {%0,%1,%2,%3};"
        : "+f"(c[0]), "+f"(c[1]), "+f"(c[2]), "+f"(c[3])
        : "r"(a[0]), "r"(a[1]), "r"(a[2]), "r"(a[3]), "r"(b[0]), "r"(b[1]));
}

// ---- init ----
__global__ void init_kernel() {
    const int i = blockIdx.x * 256 + threadIdx.x;
    if (i < BB * UU) {
        g_sbf[0][0][i] = __ushort_as_bfloat16(0);
        g_sbf[0][1][i] = __ushort_as_bfloat16(0);
    }
    if (i < 16 * 32) g_cnt[i] = 0u;
}

// ---- prep: transpose + hi/lo split of K and R ----
__global__ void prep_kernel(const float* __restrict__ Kw, const float* __restrict__ Rm) {
    const int gb = blockIdx.x;
    const int i = (gb & 1023) * 256 + threadIdx.x;
    const int n = i >> 9, k = i & 511;
    if (gb < 1024) {
        const float v = __ldg(&Kw[(size_t)k * UU + n]);
        const __nv_bfloat16 h = __float2bfloat16(v);
        g_Bh[i] = h;
        g_Bl[i] = __float2bfloat16(v - __bfloat162float(h));
    } else {
        const float v = __ldg(&Rm[(size_t)k * UU + n]);
        const __nv_bfloat16 h = __float2bfloat16(v);
        g_Rth[i] = h;
        g_Rtl[i] = __float2bfloat16(v - __bfloat162float(h));
    }
}

// ---- 1) conv with register sliding window ----
__global__ __launch_bounds__(256) void conv_kernel(const float* __restrict__ x,
                                                   const float* __restrict__ pw,
                                                   const float* __restrict__ pb) {
    const int tc = blockIdx.x;
    const int b  = blockIdx.y;
    const int wc = blockIdx.z;
    const int tid = threadIdx.x;
    const int wp = tid & 63;
    const int tg = tid >> 6;
    const int w = wc * 128 + wp * 2;
    const int tstart = tc * 64 + tg * 16;

    float cf[PP];
#pragma unroll
    for (int k = 0; k < PP; k++) cf[k] = __ldg(&pw[k]);
    const float bias = __ldg(&pb[0]);

    const float2* xp = (const float2*)(x + (size_t)b * TT * WW + w);
    float2 win[16];
#pragma unroll
    for (int i = 0; i < 16; i++)
        win[i] = xp[(size_t)(tstart + i) * (WW / 2)];

#pragma unroll
    for (int j = 0; j < 16; j++) {
        const int t = tstart + j;
        if (t < TP) {
            float ox = bias, oy = bias;
#pragma unroll
            for (int k = 0; k < PP; k++) {
                const float2 v = win[(j + k) & 15];
                ox += cf[k] * v.x;
                oy += cf[k] * v.y;
            }
            const __nv_bfloat16 hx = __float2bfloat16(ox);
            const __nv_bfloat16 lx = __float2bfloat16(ox - __bfloat162float(hx));
            const __nv_bfloat16 hy = __float2bfloat16(oy);
            const __nv_bfloat16 ly = __float2bfloat16(oy - __bfloat162float(hy));
            const uint32_t hw = (uint32_t)__bfloat16_as_ushort(hx) |
                                ((uint32_t)__bfloat16_as_ushort(hy) << 16);
            const uint32_t lw = (uint32_t)__bfloat16_as_ushort(lx) |
                                ((uint32_t)__bfloat16_as_ushort(ly) << 16);
            const size_t idx = ((size_t)b * TP + t) * WW + w;
            *(uint32_t*)&g_Ah[idx] = hw;
            *(uint32_t*)&g_Al[idx] = lw;
            const int tl = t + PP;
            if (tl < TT) win[j & 15] = xp[(size_t)tl * (WW / 2)];
        }
    }
}

// ---- 2) pre = syn @ K + bias, bf16x3 mma.sync, 3-stage, 1 sync/chunk ----
#define GEMM_SMEM (3 * 65536)
__global__ __launch_bounds__(256, 1) void gemm_mma_kernel(const float* __restrict__ bias,
                                                          float* __restrict__ C) {
    extern __shared__ __align__(1024) char smem[];
    const uint32_t sb = smem_u32(smem);
    const int tid = threadIdx.x, lane = tid & 31, wid = tid >> 5;
    const int warp_m = wid & 3, warp_n = wid >> 2;
    const size_t m0 = (size_t)blockIdx.y * 128;
    const int n0 = blockIdx.x * 128;

    float acc[2][8][4];
#pragma unroll
    for (int i = 0; i < 2; i++)
#pragma unroll
        for (int j = 0; j < 8; j++)
#pragma unroll
            for (int q = 0; q < 4; q++) acc[i][j][q] = 0.0f;

    const int lcol = tid & 7, lrow = tid >> 3;
    auto load_stage = [&](int st, int k0) {
        const uint32_t sst = sb + (uint32_t)(st * 65536);
#pragma unroll
        for (int buf = 0; buf < 4; buf++) {
            const __nv_bfloat16* src = (buf == 0) ? g_Ah : (buf == 1) ? g_Al
                                     : (buf == 2) ? g_Bh : g_Bl;
            const size_t rbase = (buf < 2) ? m0 : (size_t)n0;
            const uint32_t sbuf = sst + buf * 16384;
#pragma unroll
            for (int i = 0; i < 4; i++) {
                const int row = lrow + 32 * i;
                cpa16(sbuf + SWZ((uint32_t)(row * 128 + lcol * 16)),
                      src + (rbase + row) * 512 + k0 + lcol * 8);
            }
        }
    };

    load_stage(0, 0);
    CP_COMMIT();
    load_stage(1, 64);
    CP_COMMIT();

    const int rsel = lane >> 3, rlow = lane & 7;
    const int radd = (rsel & 1) << 3, cadd = rsel >> 1;

    for (int c = 0; c < 8; c++) {
        if (c < 7) { CP_WAIT(1); } else { CP_WAIT(0); }
        __syncthreads();   // publish stage c AND retire all reads of stage (c-1)%3
        if (c + 2 < 8) {   // safe: issued only after the sync above
            load_stage((c + 2) % 3, (c + 2) << 6);
            CP_COMMIT();
        }

        const uint32_t ss = sb + (uint32_t)((c % 3) * 65536);
#pragma unroll
        for (int ks = 0; ks < 4; ks++) {
            uint32_t a[2][2][4];
#pragma unroll
            for (int h = 0; h < 2; h++)
#pragma unroll
                for (int mf = 0; mf < 2; mf++) {
                    const int row = warp_m * 32 + mf * 16 + radd + rlow;
                    const int col = ks * 2 + cadd;
                    const uint32_t ad = ss + h * 16384 + SWZ((uint32_t)(row * 128 + col * 16));
                    LDSM4(a[h][mf][0], a[h][mf][1], a[h][mf][2], a[h][mf][3], ad);
                }
            uint32_t b[2][8][2];
#pragma unroll
            for (int h = 0; h < 2; h++)
#pragma unroll
                for (int pr = 0; pr < 4; pr++) {
                    const int row = warp_n * 64 + pr * 16 + radd + rlow;
                    const int col = ks * 2 + cadd;
                    const uint32_t ad = ss + 32768 + h * 16384 +
                                        SWZ((uint32_t)(row * 128 + col * 16));
                    uint32_t r0, r1, r2, r3;
                    LDSM4(r0, r1, r2, r3, ad);
                    b[h][pr * 2][0] = r0; b[h][pr * 2 + 1][0] = r1;
                    b[h][pr * 2][1] = r2; b[h][pr * 2 + 1][1] = r3;
                }
#pragma unroll
            for (int mf = 0; mf < 2; mf++)
#pragma unroll
                for (int nf = 0; nf < 8; nf++) {
                    mma_bf16(acc[mf][nf], a[0][mf], b[0][nf]);
                    mma_bf16(acc[mf][nf], a[0][mf], b[1][nf]);
                    mma_bf16(acc[mf][nf], a[1][mf], b[0][nf]);
                }
        }
    }

    // ---- coalesced epilogue: stage tile in SMEM (stride 132), stream rows ----
    __syncthreads();   // all MMA reads of smem done; reuse as fp32 tile
    float* ep = (float*)smem;
#pragma unroll
    for (int mf = 0; mf < 2; mf++) {
        const int row = warp_m * 32 + mf * 16 + (lane >> 2);
#pragma unroll
        for (int nf = 0; nf < 8; nf++) {
            const int col = warp_n * 64 + nf * 8 + (lane & 3) * 2;
            float* bp = ep + row * 132 + col;
            bp[0] = acc[mf][nf][0]; bp[1] = acc[mf][nf][1];
            bp[8 * 132] = acc[mf][nf][2]; bp[8 * 132 + 1] = acc[mf][nf][3];
        }
    }
    __syncthreads();
    const float4 bv = __ldg((const float4*)&bias[n0 + lane * 4]);
#pragma unroll
    for (int it = 0; it < 16; it++) {
        const int row = wid * 16 + it;
        const float* sp = ep + row * 132 + lane * 4;
        float4 v = make_float4(sp[0] + bv.x, sp[1] + bv.y, sp[2] + bv.z, sp[3] + bv.w);
        *(float4*)&C[(m0 + row) * 512 + n0 + lane * 4] = v;
    }
}

// ---- 3) persistent recurrence (R11, frozen) ----
#define RNN_SMEM 86016
__global__ __launch_bounds__(256, 2) void rnn_tc_kernel(float* __restrict__ C) {
    extern __shared__ __align__(1024) char smem[];
    const uint32_t sb = smem_u32(smem);
    float* buf = (float*)(smem + 65536);
    const uint32_t preb = sb + 81920;

    const int tid = threadIdx.x, lane = tid & 31, wid = tid >> 5;
    const int bt = blockIdx.x, ut = blockIdx.y;
    const int n0 = ut << 5, b0 = bt << 4;

    const int rsel = lane >> 3, rlow = lane & 7;
    const int radd = (rsel & 1) << 3, cadd = rsel >> 1;
    const uint32_t rchunk = sb + (uint32_t)(wid << 12);
    const uint32_t schunk_hi = sb + (uint32_t)(wid << 11);
    const uint32_t schunk_lo = sb + 32768 + (uint32_t)(wid << 11);

    const int e_b = tid >> 4;
    const int e_u = (tid & 15) << 1;
    const int bglob = b0 + e_b;
    const size_t srow = (size_t)bglob * UU + n0 + e_u;
    unsigned* const cnt = &g_cnt[bt * 32];

#pragma unroll
    for (int i = 0; i < 8; i++) {
        const int unit = tid + (i << 8);
        const int chunk = unit >> 8, rem = unit & 255;
        const int row = rem >> 3, col = rem & 7;
        const uint32_t soff = (uint32_t)(chunk << 12) + SWZ((uint32_t)(row * 128 + col * 16));
        const size_t gidx = (size_t)(n0 + row) * 512 + chunk * 64 + col * 8;
        cpa16(sb + soff, g_Rth + gidx);
        cpa16(sb + 32768 + soff, g_Rtl + gidx);
    }
    if (tid < 128) {
        const int row = tid >> 3, col = (tid & 7) << 2;
        cpa16(preb + (uint32_t)(row * 128 + col * 4),
              &C[((size_t)(b0 + row) * TP) * UU + n0 + col]);
    }
    CP_COMMIT();
    CP_WAIT(0);
    __syncthreads();

    uint32_t bfr[2][4][4][2];
#pragma unroll
    for (int h = 0; h < 2; h++)
#pragma unroll
        for (int pr = 0; pr < 2; pr++)
#pragma unroll
            for (int ks = 0; ks < 4; ks++) {
                const int row = pr * 16 + radd + rlow;
                const int col = ks * 2 + cadd;
                const uint32_t ad = rchunk + h * 32768 +
                                    SWZ((uint32_t)(row * 128 + col * 16));
                uint32_t r0, r1, r2, r3;
                LDSM4(r0, r1, r2, r3, ad);
                bfr[h][pr * 2][ks][0] = r0; bfr[h][pr * 2 + 1][ks][0] = r1;
                bfr[h][pr * 2][ks][1] = r2; bfr[h][pr * 2 + 1][ks][1] = r3;
            }
    __syncthreads();

    for (int t = 0; t < TP; t++) {
        const int p = t & 1;
        if (t > 0 && tid == 0) {
            const unsigned target = (unsigned)(t << 4);
            while (ld_acq(cnt) < target) {}
        }
        __syncthreads();

        const __nv_bfloat16* sh_g = g_sbf[p][0];
        const __nv_bfloat16* sl_g = g_sbf[p][1];
        const size_t gb2 = (size_t)b0 * 512 + (size_t)(wid << 6);
#pragma unroll
        for (int i = 0; i < 4; i++) {
            const int unit = lane + (i << 5);
            const int row = unit >> 3, col = unit & 7;
            const uint32_t soff = SWZ((uint32_t)(row * 128 + col * 16));
            const size_t gidx = gb2 + (size_t)row * 512 + col * 8;
            cpa16(schunk_hi + soff, sh_g + gidx);
            cpa16(schunk_lo + soff, sl_g + gidx);
        }
        if (t + 1 < TP && tid < 128) {
            const int row = tid >> 3, col = (tid & 7) << 2;
            cpa16(preb + (uint32_t)(((t + 1) & 1) << 11) + (uint32_t)(row * 128 + col * 4),
                  &C[((size_t)(b0 + row) * TP + (t + 1)) * UU + n0 + col]);
        }
        CP_COMMIT();
        CP_WAIT(0);

        float acc[4][4];
#pragma unroll
        for (int nf = 0; nf < 4; nf++)
#pragma unroll
            for (int q = 0; q < 4; q++) acc[nf][q] = 0.0f;

#pragma unroll
        for (int ks = 0; ks < 4; ks++) {
            uint32_t ah[4], al[4];
            const int row = radd + rlow;
            const int col = ks * 2 + cadd;
            const uint32_t off = SWZ((uint32_t)(row * 128 + col * 16));
            LDSM4(ah[0], ah[1], ah[2], ah[3], schunk_hi + off);
            LDSM4(al[0], al[1], al[2], al[3], schunk_lo + off);
#pragma unroll
            for (int nf = 0; nf < 4; nf++) {
                mma_bf16(acc[nf], ah, bfr[0][nf][ks]);
                mma_bf16(acc[nf], ah, bfr[1][nf][ks]);
                mma_bf16(acc[nf], al, bfr[0][nf][ks]);
            }
        }

#pragma unroll
        for (int nf = 0; nf < 4; nf++) {
            const int row = lane >> 2;
            const int col = nf * 8 + ((lane & 3) << 1);
            float* bp = buf + (wid << 9) + row * 32 + col;
            bp[0] = acc[nf][0]; bp[1] = acc[nf][1];
            bp[256] = acc[nf][2]; bp[257] = acc[nf][3];
        }
        __syncthreads();

        const float2* b2 = (const float2*)buf;
        float2 s = b2[tid];
#pragma unroll
        for (int w = 1; w < 8; w++) {
            const float2 v = b2[(w << 8) + tid];
            s.x += v.x; s.y += v.y;
        }

        const float2 pre = *(const float2*)(smem + 81920 + ((t & 1) << 11) +
                                            ((e_b * 32 + e_u) << 2));
        const float o[2] = {pre.x + s.x, pre.y + s.y};
        float nn[2];
        uint32_t hw = 0, lw = 0;
#pragma unroll
        for (int j = 0; j < 2; j++) {
            const float n = 1.0f / (1.0f + __expf(-3.0f * o[j]));
            nn[j] = n;
            const float st = o[j] / (1.0f + __expf(2.0f * n - 1.0f));
            const __nv_bfloat16 h = __float2bfloat16(st);
            const __nv_bfloat16 l = __float2bfloat16(st - __bfloat162float(h));
            hw |= (uint32_t)__bfloat16_as_ushort(h) << (j * 16);
            lw |= (uint32_t)__bfloat16_as_ushort(l) << (j * 16);
        }
        *(uint32_t*)&g_sbf[p ^ 1][0][srow] = hw;
        *(uint32_t*)&g_sbf[p ^ 1][1][srow] = lw;
        __syncthreads();
        if (tid == 0) red_rel(cnt);

        const size_t crow = ((size_t)bglob * TP + t) * UU + n0 + e_u;
        *(float2*)&C[crow] = make_float2(nn[0], nn[1]);
    }
}

extern "C" void kernel_launch(void* const* d_in, const int* in_sizes, int n_in,
                              void* d_out, int out_size) {
    const float* x    = (const float*)d_in[0];
    const float* pw   = (const float*)d_in[1];
    const float* pb   = (const float*)d_in[2];
    const float* Kw   = (const float*)d_in[3];
    const float* Rm   = (const float*)d_in[4];
    const float* bias = (const float*)d_in[5];
    float* out = (float*)d_out;

    cudaFuncSetAttribute(gemm_mma_kernel,
                         cudaFuncAttributeMaxDynamicSharedMemorySize, GEMM_SMEM);
    cudaFuncSetAttribute(rnn_tc_kernel,
                         cudaFuncAttributeMaxDynamicSharedMemorySize, RNN_SMEM);

    init_kernel<<<(BB * UU) / 256, 256>>>();
    prep_kernel<<<2048, 256>>>(Kw, Rm);
    conv_kernel<<<dim3(16, BB, 4), 256>>>(x, pw, pb);
    gemm_mma_kernel<<<dim3(UU / 128, MTOT / 128), 256, GEMM_SMEM>>>(bias, out);
    rnn_tc_kernel<<<dim3(16, 16), 256, RNN_SMEM>>>(out);
}

// round 14
// speedup vs baseline: 1.0675x; 1.0675x over previous
#include <cuda_runtime.h>
#include <cuda_bf16.h>
#include <cstdint>

#define BB 256
#define TT 1024
#define WW 512
#define UU 512
#define PP 16
#define TP (TT - PP + 1)
#define MTOT (BB * TP)

__device__ __align__(16) __nv_bfloat16 g_Ah[(size_t)MTOT * WW];
__device__ __align__(16) __nv_bfloat16 g_Al[(size_t)MTOT * WW];
__device__ __align__(16) __nv_bfloat16 g_Bh[WW * UU];    // K^T hi [n][k]
__device__ __align__(16) __nv_bfloat16 g_Bl[WW * UU];    // K^T lo [n][k]
__device__ __align__(16) __nv_bfloat16 g_Rth[UU * UU];   // R^T hi [n][k]
__device__ __align__(16) __nv_bfloat16 g_Rtl[UU * UU];   // R^T lo [n][k]
__device__ __align__(16) __nv_bfloat16 g_sbf[2][2][BB * UU]; // [parity][hi/lo]
__device__ unsigned g_flags[16][16 * 32];  // [batch-group][u-tile], 128B padded

typedef unsigned long long u64;
__device__ __forceinline__ unsigned ld_acq(const unsigned* p) {
    unsigned v;
    asm volatile("ld.global.acquire.gpu.u32 %0, [%1];" : "=r"(v) : "l"(p) : "memory");
    return v;
}
__device__ __forceinline__ void st_rel(unsigned* p, unsigned v) {
    asm volatile("st.global.release.gpu.u32 [%0], %1;" :: "l"(p), "r"(v) : "memory");
}
__device__ __forceinline__ uint32_t smem_u32(const void* p) {
    uint32_t a;
    asm("{ .reg .u64 t; cvta.to.shared.u64 t, %1; cvt.u32.u64 %0, t; }" : "=r"(a) : "l"(p));
    return a;
}
__device__ __forceinline__ void cpa16(uint32_t s, const void* g) {
    asm volatile("cp.async.cg.shared.global [%0], [%1], 16;" :: "r"(s), "l"(g) : "memory");
}
#define CP_COMMIT() asm volatile("cp.async.commit_group;" ::: "memory")
#define CP_WAIT(n)  asm volatile("cp.async.wait_group %0;" :: "n"(n) : "memory")
#define SWZ(x) ((x) ^ (((x) >> 3) & 0x70))
#define LDSM4(r0, r1, r2, r3, a) \
    asm volatile("ldmatrix.sync.aligned.m8n8.x4.shared.b16 {%0,%1,%2,%3}, [%4];" \
                 : "=r"(r0), "=r"(r1), "=r"(r2), "=r"(r3) : "r"(a))
__device__ __forceinline__ void mma_bf16(float* c, const uint32_t* a, const uint32_t* b) {
    asm volatile(
        "mma.sync.aligned.m16n8k16.row.col.f32.bf16.bf16.f32 "
        "{%0,%1,%2,%3}, {%4,%5,%6,%7}, {%8,%9}, {%0,%1,%2,%3};"
        : "+f"(c[0]), "+f"(c[1]), "+f"(c[2]), "+f"(c[3])
        : "r"(a[0]), "r"(a[1]), "r"(a[2]), "r"(a[3]), "r"(b[0]), "r"(b[1]));
}

// ---- init ----
__global__ void init_kernel() {
    const int i = blockIdx.x * 256 + threadIdx.x;
    if (i < BB * UU) {
        g_sbf[0][0][i] = __ushort_as_bfloat16(0);
        g_sbf[0][1][i] = __ushort_as_bfloat16(0);
    }
    if (i < 16 * 16 * 32) ((unsigned*)g_flags)[i] = 0u;
}

// ---- prep: transpose + hi/lo split of K and R ----
__global__ void prep_kernel(const float* __restrict__ Kw, const float* __restrict__ Rm) {
    const int gb = blockIdx.x;
    const int i = (gb & 1023) * 256 + threadIdx.x;
    const int n = i >> 9, k = i & 511;
    if (gb < 1024) {
        const float v = __ldg(&Kw[(size_t)k * UU + n]);
        const __nv_bfloat16 h = __float2bfloat16(v);
        g_Bh[i] = h;
        g_Bl[i] = __float2bfloat16(v - __bfloat162float(h));
    } else {
        const float v = __ldg(&Rm[(size_t)k * UU + n]);
        const __nv_bfloat16 h = __float2bfloat16(v);
        g_Rth[i] = h;
        g_Rtl[i] = __float2bfloat16(v - __bfloat162float(h));
    }
}

// ---- 1) conv with register sliding window ----
__global__ __launch_bounds__(256) void conv_kernel(const float* __restrict__ x,
                                                   const float* __restrict__ pw,
                                                   const float* __restrict__ pb) {
    const int tc = blockIdx.x;
    const int b  = blockIdx.y;
    const int wc = blockIdx.z;
    const int tid = threadIdx.x;
    const int wp = tid & 63;
    const int tg = tid >> 6;
    const int w = wc * 128 + wp * 2;
    const int tstart = tc * 64 + tg * 16;

    float cf[PP];
#pragma unroll
    for (int k = 0; k < PP; k++) cf[k] = __ldg(&pw[k]);
    const float bias = __ldg(&pb[0]);

    const float2* xp = (const float2*)(x + (size_t)b * TT * WW + w);
    float2 win[16];
#pragma unroll
    for (int i = 0; i < 16; i++)
        win[i] = xp[(size_t)(tstart + i) * (WW / 2)];

#pragma unroll
    for (int j = 0; j < 16; j++) {
        const int t = tstart + j;
        if (t < TP) {
            float ox = bias, oy = bias;
#pragma unroll
            for (int k = 0; k < PP; k++) {
                const float2 v = win[(j + k) & 15];
                ox += cf[k] * v.x;
                oy += cf[k] * v.y;
            }
            const __nv_bfloat16 hx = __float2bfloat16(ox);
            const __nv_bfloat16 lx = __float2bfloat16(ox - __bfloat162float(hx));
            const __nv_bfloat16 hy = __float2bfloat16(oy);
            const __nv_bfloat16 ly = __float2bfloat16(oy - __bfloat162float(hy));
            const uint32_t hw = (uint32_t)__bfloat16_as_ushort(hx) |
                                ((uint32_t)__bfloat16_as_ushort(hy) << 16);
            const uint32_t lw = (uint32_t)__bfloat16_as_ushort(lx) |
                                ((uint32_t)__bfloat16_as_ushort(ly) << 16);
            const size_t idx = ((size_t)b * TP + t) * WW + w;
            *(uint32_t*)&g_Ah[idx] = hw;
            *(uint32_t*)&g_Al[idx] = lw;
            const int tl = t + PP;
            if (tl < TT) win[j & 15] = xp[(size_t)tl * (WW / 2)];
        }
    }
}

// ---- 2) pre = syn @ K + bias, bf16x3 mma.sync, 3-stage (R12 version) ----
#define GEMM_SMEM (3 * 65536)
__global__ __launch_bounds__(256, 1) void gemm_mma_kernel(const float* __restrict__ bias,
                                                          float* __restrict__ C) {
    extern __shared__ __align__(1024) char smem[];
    const uint32_t sb = smem_u32(smem);
    const int tid = threadIdx.x, lane = tid & 31, wid = tid >> 5;
    const int warp_m = wid & 3, warp_n = wid >> 2;
    const size_t m0 = (size_t)blockIdx.y * 128;
    const int n0 = blockIdx.x * 128;

    float acc[2][8][4];
#pragma unroll
    for (int i = 0; i < 2; i++)
#pragma unroll
        for (int j = 0; j < 8; j++)
#pragma unroll
            for (int q = 0; q < 4; q++) acc[i][j][q] = 0.0f;

    const int lcol = tid & 7, lrow = tid >> 3;
    auto load_stage = [&](int st, int k0) {
        const uint32_t sst = sb + (uint32_t)(st * 65536);
#pragma unroll
        for (int buf = 0; buf < 4; buf++) {
            const __nv_bfloat16* src = (buf == 0) ? g_Ah : (buf == 1) ? g_Al
                                     : (buf == 2) ? g_Bh : g_Bl;
            const size_t rbase = (buf < 2) ? m0 : (size_t)n0;
            const uint32_t sbuf = sst + buf * 16384;
#pragma unroll
            for (int i = 0; i < 4; i++) {
                const int row = lrow + 32 * i;
                cpa16(sbuf + SWZ((uint32_t)(row * 128 + lcol * 16)),
                      src + (rbase + row) * 512 + k0 + lcol * 8);
            }
        }
    };

    load_stage(0, 0);
    CP_COMMIT();
    load_stage(1, 64);
    CP_COMMIT();

    const int rsel = lane >> 3, rlow = lane & 7;
    const int radd = (rsel & 1) << 3, cadd = rsel >> 1;

    for (int c = 0; c < 8; c++) {
        if (c + 2 < 8) {
            load_stage((c + 2) % 3, (c + 2) << 6);
            CP_COMMIT();
        }
        if (c < 6) { CP_WAIT(2); } else if (c == 6) { CP_WAIT(1); } else { CP_WAIT(0); }
        __syncthreads();

        const uint32_t ss = sb + (uint32_t)((c % 3) * 65536);
#pragma unroll
        for (int ks = 0; ks < 4; ks++) {
            uint32_t a[2][2][4];
#pragma unroll
            for (int h = 0; h < 2; h++)
#pragma unroll
                for (int mf = 0; mf < 2; mf++) {
                    const int row = warp_m * 32 + mf * 16 + radd + rlow;
                    const int col = ks * 2 + cadd;
                    const uint32_t ad = ss + h * 16384 + SWZ((uint32_t)(row * 128 + col * 16));
                    LDSM4(a[h][mf][0], a[h][mf][1], a[h][mf][2], a[h][mf][3], ad);
                }
            uint32_t b[2][8][2];
#pragma unroll
            for (int h = 0; h < 2; h++)
#pragma unroll
                for (int pr = 0; pr < 4; pr++) {
                    const int row = warp_n * 64 + pr * 16 + radd + rlow;
                    const int col = ks * 2 + cadd;
                    const uint32_t ad = ss + 32768 + h * 16384 +
                                        SWZ((uint32_t)(row * 128 + col * 16));
                    uint32_t r0, r1, r2, r3;
                    LDSM4(r0, r1, r2, r3, ad);
                    b[h][pr * 2][0] = r0; b[h][pr * 2 + 1][0] = r1;
                    b[h][pr * 2][1] = r2; b[h][pr * 2 + 1][1] = r3;
                }
#pragma unroll
            for (int mf = 0; mf < 2; mf++)
#pragma unroll
                for (int nf = 0; nf < 8; nf++) {
                    mma_bf16(acc[mf][nf], a[0][mf], b[0][nf]);
                    mma_bf16(acc[mf][nf], a[0][mf], b[1][nf]);
                    mma_bf16(acc[mf][nf], a[1][mf], b[0][nf]);
                }
        }
        __syncthreads();
    }

#pragma unroll
    for (int mf = 0; mf < 2; mf++) {
        const int row = warp_m * 32 + mf * 16 + (lane >> 2);
        const size_t gr0 = (m0 + row) * 512;
        const size_t gr1 = (m0 + row + 8) * 512;
#pragma unroll
        for (int nf = 0; nf < 8; nf++) {
            const int col = n0 + warp_n * 64 + nf * 8 + (lane & 3) * 2;
            const float2 bv = *(const float2*)&bias[col];
            *(float2*)&C[gr0 + col] =
                make_float2(acc[mf][nf][0] + bv.x, acc[mf][nf][1] + bv.y);
            *(float2*)&C[gr1 + col] =
                make_float2(acc[mf][nf][2] + bv.x, acc[mf][nf][3] + bv.y);
        }
    }
}

// ---- 3) persistent recurrence, per-warp producer-pair waits ----
#define RNN_SMEM 86016
__global__ __launch_bounds__(256, 2) void rnn_tc_kernel(float* __restrict__ C) {
    extern __shared__ __align__(1024) char smem[];
    const uint32_t sb = smem_u32(smem);
    float* buf = (float*)(smem + 65536);
    const uint32_t preb = sb + 81920;

    const int tid = threadIdx.x, lane = tid & 31, wid = tid >> 5;
    const int bt = blockIdx.x, ut = blockIdx.y;
    const int n0 = ut << 5, b0 = bt << 4;

    const int rsel = lane >> 3, rlow = lane & 7;
    const int radd = (rsel & 1) << 3, cadd = rsel >> 1;
    const uint32_t rchunk = sb + (uint32_t)(wid << 12);
    const uint32_t schunk_hi = sb + (uint32_t)(wid << 11);
    const uint32_t schunk_lo = sb + 32768 + (uint32_t)(wid << 11);

    const int e_b = tid >> 4;
    const int e_u = (tid & 15) << 1;
    const int bglob = b0 + e_b;
    const size_t srow = (size_t)bglob * UU + n0 + e_u;
    // warp w consumes k in [64w,64w+64) -> producers are u-tiles 2w and 2w+1
    const unsigned* myflag = (lane < 2) ? &g_flags[bt][((wid << 1) | lane) * 32] : 0;

#pragma unroll
    for (int i = 0; i < 8; i++) {
        const int unit = tid + (i << 8);
        const int chunk = unit >> 8, rem = unit & 255;
        const int row = rem >> 3, col = rem & 7;
        const uint32_t soff = (uint32_t)(chunk << 12) + SWZ((uint32_t)(row * 128 + col * 16));
        const size_t gidx = (size_t)(n0 + row) * 512 + chunk * 64 + col * 8;
        cpa16(sb + soff, g_Rth + gidx);
        cpa16(sb + 32768 + soff, g_Rtl + gidx);
    }
    if (tid < 128) {
        const int row = tid >> 3, col = (tid & 7) << 2;
        cpa16(preb + (uint32_t)(row * 128 + col * 4),
              &C[((size_t)(b0 + row) * TP) * UU + n0 + col]);
    }
    CP_COMMIT();
    CP_WAIT(0);
    __syncthreads();

    uint32_t bfr[2][4][4][2];
#pragma unroll
    for (int h = 0; h < 2; h++)
#pragma unroll
        for (int pr = 0; pr < 2; pr++)
#pragma unroll
            for (int ks = 0; ks < 4; ks++) {
                const int row = pr * 16 + radd + rlow;
                const int col = ks * 2 + cadd;
                const uint32_t ad = rchunk + h * 32768 +
                                    SWZ((uint32_t)(row * 128 + col * 16));
                uint32_t r0, r1, r2, r3;
                LDSM4(r0, r1, r2, r3, ad);
                bfr[h][pr * 2][ks][0] = r0; bfr[h][pr * 2 + 1][ks][0] = r1;
                bfr[h][pr * 2][ks][1] = r2; bfr[h][pr * 2 + 1][ks][1] = r3;
            }
    __syncthreads();

    for (int t = 0; t < TP; t++) {
        const int p = t & 1;
        // per-warp wait: lanes 0,1 poll this warp's two producer flags
        if (t > 0) {
            if (lane < 2) {
                while (ld_acq(myflag) < (unsigned)t) {}
            }
            __syncwarp();
        }

        const __nv_bfloat16* sh_g = g_sbf[p][0];
        const __nv_bfloat16* sl_g = g_sbf[p][1];
        const size_t gb2 = (size_t)b0 * 512 + (size_t)(wid << 6);
#pragma unroll
        for (int i = 0; i < 4; i++) {
            const int unit = lane + (i << 5);
            const int row = unit >> 3, col = unit & 7;
            const uint32_t soff = SWZ((uint32_t)(row * 128 + col * 16));
            const size_t gidx = gb2 + (size_t)row * 512 + col * 8;
            cpa16(schunk_hi + soff, sh_g + gidx);
            cpa16(schunk_lo + soff, sl_g + gidx);
        }
        if (t + 1 < TP && tid < 128) {
            const int row = tid >> 3, col = (tid & 7) << 2;
            cpa16(preb + (uint32_t)(((t + 1) & 1) << 11) + (uint32_t)(row * 128 + col * 4),
                  &C[((size_t)(b0 + row) * TP + (t + 1)) * UU + n0 + col]);
        }
        CP_COMMIT();
        CP_WAIT(0);

        float acc[4][4];
#pragma unroll
        for (int nf = 0; nf < 4; nf++)
#pragma unroll
            for (int q = 0; q < 4; q++) acc[nf][q] = 0.0f;

#pragma unroll
        for (int ks = 0; ks < 4; ks++) {
            uint32_t ah[4], al[4];
            const int row = radd + rlow;
            const int col = ks * 2 + cadd;
            const uint32_t off = SWZ((uint32_t)(row * 128 + col * 16));
            LDSM4(ah[0], ah[1], ah[2], ah[3], schunk_hi + off);
            LDSM4(al[0], al[1], al[2], al[3], schunk_lo + off);
#pragma unroll
            for (int nf = 0; nf < 4; nf++) {
                mma_bf16(acc[nf], ah, bfr[0][nf][ks]);
                mma_bf16(acc[nf], ah, bfr[1][nf][ks]);
                mma_bf16(acc[nf], al, bfr[0][nf][ks]);
            }
        }

#pragma unroll
        for (int nf = 0; nf < 4; nf++) {
            const int row = lane >> 2;
            const int col = nf * 8 + ((lane & 3) << 1);
            float* bp = buf + (wid << 9) + row * 32 + col;
            bp[0] = acc[nf][0]; bp[1] = acc[nf][1];
            bp[256] = acc[nf][2]; bp[257] = acc[nf][3];
        }
        __syncthreads();   // (d) partials + pre visible to all

        const float2* b2 = (const float2*)buf;
        float2 s = b2[tid];
#pragma unroll
        for (int w = 1; w < 8; w++) {
            const float2 v = b2[(w << 8) + tid];
            s.x += v.x; s.y += v.y;
        }

        const float2 pre = *(const float2*)(smem + 81920 + ((t & 1) << 11) +
                                            ((e_b * 32 + e_u) << 2));
        const float o[2] = {pre.x + s.x, pre.y + s.y};
        float nn[2];
        uint32_t hw = 0, lw = 0;
#pragma unroll
        for (int j = 0; j < 2; j++) {
            const float n = 1.0f / (1.0f + __expf(-3.0f * o[j]));
            nn[j] = n;
            const float st = o[j] / (1.0f + __expf(2.0f * n - 1.0f));
            const __nv_bfloat16 h = __float2bfloat16(st);
            const __nv_bfloat16 l = __float2bfloat16(st - __bfloat162float(h));
            hw |= (uint32_t)__bfloat16_as_ushort(h) << (j * 16);
            lw |= (uint32_t)__bfloat16_as_ushort(l) << (j * 16);
        }
        *(uint32_t*)&g_sbf[p ^ 1][0][srow] = hw;
        *(uint32_t*)&g_sbf[p ^ 1][1][srow] = lw;
        __syncthreads();   // (e) all state stores done before release
        if (tid == 0) st_rel(&g_flags[bt][ut * 32], (unsigned)(t + 1));

        const size_t crow = ((size_t)bglob * TP + t) * UU + n0 + e_u;
        *(float2*)&C[crow] = make_float2(nn[0], nn[1]);
    }
}

extern "C" void kernel_launch(void* const* d_in, const int* in_sizes, int n_in,
                              void* d_out, int out_size) {
    const float* x    = (const float*)d_in[0];
    const float* pw   = (const float*)d_in[1];
    const float* pb   = (const float*)d_in[2];
    const float* Kw   = (const float*)d_in[3];
    const float* Rm   = (const float*)d_in[4];
    const float* bias = (const float*)d_in[5];
    float* out = (float*)d_out;

    cudaFuncSetAttribute(gemm_mma_kernel,
                         cudaFuncAttributeMaxDynamicSharedMemorySize, GEMM_SMEM);
    cudaFuncSetAttribute(rnn_tc_kernel,
                         cudaFuncAttributeMaxDynamicSharedMemorySize, RNN_SMEM);

    init_kernel<<<(BB * UU) / 256, 256>>>();
    prep_kernel<<<2048, 256>>>(Kw, Rm);
    conv_kernel<<<dim3(16, BB, 4), 256>>>(x, pw, pb);
    gemm_mma_kernel<<<dim3(UU / 128, MTOT / 128), 256, GEMM_SMEM>>>(bias, out);
    rnn_tc_kernel<<<dim3(16, 16), 256, RNN_SMEM>>>(out);
}

// round 15
// speedup vs baseline: 1.1166x; 1.0460x over previous
#include <cuda_runtime.h>
#include <cuda_bf16.h>
#include <cuda_fp16.h>
#include <cstdint>

#define BB 256
#define TT 1024
#define WW 512
#define UU 512
#define PP 16
#define TP (TT - PP + 1)
#define MTOT (BB * TP)

__device__ __align__(16) __nv_bfloat16 g_Ah[(size_t)MTOT * WW];
__device__ __align__(16) __nv_bfloat16 g_Al[(size_t)MTOT * WW];
__device__ __align__(16) __nv_bfloat16 g_Bh[WW * UU];    // K^T hi [n][k] bf16
__device__ __align__(16) __nv_bfloat16 g_Bl[WW * UU];    // K^T lo [n][k] bf16
__device__ __align__(16) __half g_Rh16[UU * UU];         // R^T hi [n][k] fp16
__device__ __align__(16) __half g_Rl16[UU * UU];         // R^T lo [n][k] fp16
__device__ __align__(16) __half g_sf16[2][BB * UU];      // state fp16 [parity]
__device__ unsigned g_flags[16][16 * 32];  // [batch-group][u-tile], 128B padded

typedef unsigned long long u64;
__device__ __forceinline__ unsigned ld_acq(const unsigned* p) {
    unsigned v;
    asm volatile("ld.global.acquire.gpu.u32 %0, [%1];" : "=r"(v) : "l"(p) : "memory");
    return v;
}
__device__ __forceinline__ void red_rel(unsigned* p) {
    asm volatile("red.release.gpu.global.add.u32 [%0], 1;" :: "l"(p) : "memory");
}
__device__ __forceinline__ uint32_t smem_u32(const void* p) {
    uint32_t a;
    asm("{ .reg .u64 t; cvta.to.shared.u64 t, %1; cvt.u32.u64 %0, t; }" : "=r"(a) : "l"(p));
    return a;
}
__device__ __forceinline__ void cpa16(uint32_t s, const void* g) {
    asm volatile("cp.async.cg.shared.global [%0], [%1], 16;" :: "r"(s), "l"(g) : "memory");
}
#define CP_COMMIT() asm volatile("cp.async.commit_group;" ::: "memory")
#define CP_WAIT(n)  asm volatile("cp.async.wait_group %0;" :: "n"(n) : "memory")
#define SWZ(x) ((x) ^ (((x) >> 3) & 0x70))
#define LDSM4(r0, r1, r2, r3, a) \
    asm volatile("ldmatrix.sync.aligned.m8n8.x4.shared.b16 {%0,%1,%2,%3}, [%4];" \
                 : "=r"(r0), "=r"(r1), "=r"(r2), "=r"(r3) : "r"(a))
__device__ __forceinline__ void mma_bf16(float* c, const uint32_t* a, const uint32_t* b) {
    asm volatile(
        "mma.sync.aligned.m16n8k16.row.col.f32.bf16.bf16.f32 "
        "{%0,%1,%2,%3}, {%4,%5,%6,%7}, {%8,%9}, {%0,%1,%2,%3};"
        : "+f"(c[0]), "+f"(c[1]), "+f"(c[2]), "+f"(c[3])
        : "r"(a[0]), "r"(a[1]), "r"(a[2]), "r"(a[3]), "r"(b[0]), "r"(b[1]));
}
__device__ __forceinline__ void mma_f16(float* c, const uint32_t* a, const uint32_t* b) {
    asm volatile(
        "mma.sync.aligned.m16n8k16.row.col.f32.f16.f16.f32 "
        "{%0,%1,%2,%3}, {%4,%5,%6,%7}, {%8,%9}, {%0,%1,%2,%3};"
        : "+f"(c[0]), "+f"(c[1]), "+f"(c[2]), "+f"(c[3])
        : "r"(a[0]), "r"(a[1]), "r"(a[2]), "r"(a[3]), "r"(b[0]), "r"(b[1]));
}

// ---- init ----
__global__ void init_kernel() {
    const int i = blockIdx.x * 256 + threadIdx.x;
    if (i < BB * UU) g_sf16[0][i] = __float2half(0.0f);
    if (i < 16 * 16 * 32) ((unsigned*)g_flags)[i] = 0u;
}

// ---- prep: transpose + hi/lo split of K (bf16) and R (fp16) ----
__global__ void prep_kernel(const float* __restrict__ Kw, const float* __restrict__ Rm) {
    const int gb = blockIdx.x;
    const int i = (gb & 1023) * 256 + threadIdx.x;
    const int n = i >> 9, k = i & 511;
    if (gb < 1024) {
        const float v = __ldg(&Kw[(size_t)k * UU + n]);
        const __nv_bfloat16 h = __float2bfloat16(v);
        g_Bh[i] = h;
        g_Bl[i] = __float2bfloat16(v - __bfloat162float(h));
    } else {
        const float v = __ldg(&Rm[(size_t)k * UU + n]);
        const __half h = __float2half(v);
        g_Rh16[i] = h;
        g_Rl16[i] = __float2half(v - __half2float(h));
    }
}

// ---- 1) conv with register sliding window ----
__global__ __launch_bounds__(256) void conv_kernel(const float* __restrict__ x,
                                                   const float* __restrict__ pw,
                                                   const float* __restrict__ pb) {
    const int tc = blockIdx.x;
    const int b  = blockIdx.y;
    const int wc = blockIdx.z;
    const int tid = threadIdx.x;
    const int wp = tid & 63;
    const int tg = tid >> 6;
    const int w = wc * 128 + wp * 2;
    const int tstart = tc * 64 + tg * 16;

    float cf[PP];
#pragma unroll
    for (int k = 0; k < PP; k++) cf[k] = __ldg(&pw[k]);
    const float bias = __ldg(&pb[0]);

    const float2* xp = (const float2*)(x + (size_t)b * TT * WW + w);
    float2 win[16];
#pragma unroll
    for (int i = 0; i < 16; i++)
        win[i] = xp[(size_t)(tstart + i) * (WW / 2)];

#pragma unroll
    for (int j = 0; j < 16; j++) {
        const int t = tstart + j;
        if (t < TP) {
            float ox = bias, oy = bias;
#pragma unroll
            for (int k = 0; k < PP; k++) {
                const float2 v = win[(j + k) & 15];
                ox += cf[k] * v.x;
                oy += cf[k] * v.y;
            }
            const __nv_bfloat16 hx = __float2bfloat16(ox);
            const __nv_bfloat16 lx = __float2bfloat16(ox - __bfloat162float(hx));
            const __nv_bfloat16 hy = __float2bfloat16(oy);
            const __nv_bfloat16 ly = __float2bfloat16(oy - __bfloat162float(hy));
            const uint32_t hw = (uint32_t)__bfloat16_as_ushort(hx) |
                                ((uint32_t)__bfloat16_as_ushort(hy) << 16);
            const uint32_t lw = (uint32_t)__bfloat16_as_ushort(lx) |
                                ((uint32_t)__bfloat16_as_ushort(ly) << 16);
            const size_t idx = ((size_t)b * TP + t) * WW + w;
            *(uint32_t*)&g_Ah[idx] = hw;
            *(uint32_t*)&g_Al[idx] = lw;
            const int tl = t + PP;
            if (tl < TT) win[j & 15] = xp[(size_t)tl * (WW / 2)];
        }
    }
}

// ---- 2) pre = syn @ K + bias, bf16x3 mma.sync, 3-stage (R12/R14 version) ----
#define GEMM_SMEM (3 * 65536)
__global__ __launch_bounds__(256, 1) void gemm_mma_kernel(const float* __restrict__ bias,
                                                          float* __restrict__ C) {
    extern __shared__ __align__(1024) char smem[];
    const uint32_t sb = smem_u32(smem);
    const int tid = threadIdx.x, lane = tid & 31, wid = tid >> 5;
    const int warp_m = wid & 3, warp_n = wid >> 2;
    const size_t m0 = (size_t)blockIdx.y * 128;
    const int n0 = blockIdx.x * 128;

    float acc[2][8][4];
#pragma unroll
    for (int i = 0; i < 2; i++)
#pragma unroll
        for (int j = 0; j < 8; j++)
#pragma unroll
            for (int q = 0; q < 4; q++) acc[i][j][q] = 0.0f;

    const int lcol = tid & 7, lrow = tid >> 3;
    auto load_stage = [&](int st, int k0) {
        const uint32_t sst = sb + (uint32_t)(st * 65536);
#pragma unroll
        for (int buf = 0; buf < 4; buf++) {
            const __nv_bfloat16* src = (buf == 0) ? g_Ah : (buf == 1) ? g_Al
                                     : (buf == 2) ? g_Bh : g_Bl;
            const size_t rbase = (buf < 2) ? m0 : (size_t)n0;
            const uint32_t sbuf = sst + buf * 16384;
#pragma unroll
            for (int i = 0; i < 4; i++) {
                const int row = lrow + 32 * i;
                cpa16(sbuf + SWZ((uint32_t)(row * 128 + lcol * 16)),
                      src + (rbase + row) * 512 + k0 + lcol * 8);
            }
        }
    };

    load_stage(0, 0);
    CP_COMMIT();
    load_stage(1, 64);
    CP_COMMIT();

    const int rsel = lane >> 3, rlow = lane & 7;
    const int radd = (rsel & 1) << 3, cadd = rsel >> 1;

    for (int c = 0; c < 8; c++) {
        if (c + 2 < 8) {
            load_stage((c + 2) % 3, (c + 2) << 6);
            CP_COMMIT();
        }
        if (c < 6) { CP_WAIT(2); } else if (c == 6) { CP_WAIT(1); } else { CP_WAIT(0); }
        __syncthreads();

        const uint32_t ss = sb + (uint32_t)((c % 3) * 65536);
#pragma unroll
        for (int ks = 0; ks < 4; ks++) {
            uint32_t a[2][2][4];
#pragma unroll
            for (int h = 0; h < 2; h++)
#pragma unroll
                for (int mf = 0; mf < 2; mf++) {
                    const int row = warp_m * 32 + mf * 16 + radd + rlow;
                    const int col = ks * 2 + cadd;
                    const uint32_t ad = ss + h * 16384 + SWZ((uint32_t)(row * 128 + col * 16));
                    LDSM4(a[h][mf][0], a[h][mf][1], a[h][mf][2], a[h][mf][3], ad);
                }
            uint32_t b[2][8][2];
#pragma unroll
            for (int h = 0; h < 2; h++)
#pragma unroll
                for (int pr = 0; pr < 4; pr++) {
                    const int row = warp_n * 64 + pr * 16 + radd + rlow;
                    const int col = ks * 2 + cadd;
                    const uint32_t ad = ss + 32768 + h * 16384 +
                                        SWZ((uint32_t)(row * 128 + col * 16));
                    uint32_t r0, r1, r2, r3;
                    LDSM4(r0, r1, r2, r3, ad);
                    b[h][pr * 2][0] = r0; b[h][pr * 2 + 1][0] = r1;
                    b[h][pr * 2][1] = r2; b[h][pr * 2 + 1][1] = r3;
                }
#pragma unroll
            for (int mf = 0; mf < 2; mf++)
#pragma unroll
                for (int nf = 0; nf < 8; nf++) {
                    mma_bf16(acc[mf][nf], a[0][mf], b[0][nf]);
                    mma_bf16(acc[mf][nf], a[0][mf], b[1][nf]);
                    mma_bf16(acc[mf][nf], a[1][mf], b[0][nf]);
                }
        }
        __syncthreads();
    }

#pragma unroll
    for (int mf = 0; mf < 2; mf++) {
        const int row = warp_m * 32 + mf * 16 + (lane >> 2);
        const size_t gr0 = (m0 + row) * 512;
        const size_t gr1 = (m0 + row + 8) * 512;
#pragma unroll
        for (int nf = 0; nf < 8; nf++) {
            const int col = n0 + warp_n * 64 + nf * 8 + (lane & 3) * 2;
            const float2 bv = *(const float2*)&bias[col];
            *(float2*)&C[gr0 + col] =
                make_float2(acc[mf][nf][0] + bv.x, acc[mf][nf][1] + bv.y);
            *(float2*)&C[gr1 + col] =
                make_float2(acc[mf][nf][2] + bv.x, acc[mf][nf][3] + bv.y);
        }
    }
}

// ---- 3) persistent recurrence: fp16 state, 1 barrier/step, per-warp release ----
// SMEM: [0,64K) R fp16 hi/lo staging (state tile overlays [0,16K), 2KB/warp)
//       [64K,96K) buf double-buffered (16KB each); [96K,100K) pre double buffer.
#define RNN_SMEM 102400
__global__ __launch_bounds__(256, 2) void rnn_tc_kernel(float* __restrict__ C) {
    extern __shared__ __align__(1024) char smem[];
    const uint32_t sb = smem_u32(smem);
    const uint32_t preb = sb + 98304;

    const int tid = threadIdx.x, lane = tid & 31, wid = tid >> 5;
    const int bt = blockIdx.x, ut = blockIdx.y;
    const int n0 = ut << 5, b0 = bt << 4;

    const int rsel = lane >> 3, rlow = lane & 7;
    const int radd = (rsel & 1) << 3, cadd = rsel >> 1;
    const uint32_t rchunk = sb + (uint32_t)(wid << 12);   // R staging chunk (4KB)
    const uint32_t schunk = sb + (uint32_t)(wid << 11);   // state fp16 chunk (2KB)

    const int e_b = tid >> 4;
    const int e_u = (tid & 15) << 1;
    const int bglob = b0 + e_b;
    const size_t srow = (size_t)bglob * UU + n0 + e_u;
    const unsigned* myflag = (lane < 2) ? &g_flags[bt][((wid << 1) | lane) * 32] : 0;
    unsigned* const relflag = &g_flags[bt][ut * 32];

    // stage R^T [32n][512k] fp16 hi/lo into SMEM + prefetch pre[0]
#pragma unroll
    for (int i = 0; i < 8; i++) {
        const int unit = tid + (i << 8);
        const int chunk = unit >> 8, rem = unit & 255;
        const int row = rem >> 3, col = rem & 7;
        const uint32_t soff = (uint32_t)(chunk << 12) + SWZ((uint32_t)(row * 128 + col * 16));
        const size_t gidx = (size_t)(n0 + row) * 512 + chunk * 64 + col * 8;
        cpa16(sb + soff, g_Rh16 + gidx);
        cpa16(sb + 32768 + soff, g_Rl16 + gidx);
    }
    if (tid < 128) {
        const int row = tid >> 3, col = (tid & 7) << 2;
        cpa16(preb + (uint32_t)(row * 128 + col * 4),
              &C[((size_t)(b0 + row) * TP) * UU + n0 + col]);
    }
    CP_COMMIT();
    CP_WAIT(0);
    __syncthreads();

    uint32_t bfr[2][4][4][2];   // [hi/lo][n8][k16][reg]
#pragma unroll
    for (int h = 0; h < 2; h++)
#pragma unroll
        for (int pr = 0; pr < 2; pr++)
#pragma unroll
            for (int ks = 0; ks < 4; ks++) {
                const int row = pr * 16 + radd + rlow;
                const int col = ks * 2 + cadd;
                const uint32_t ad = rchunk + h * 32768 +
                                    SWZ((uint32_t)(row * 128 + col * 16));
                uint32_t r0, r1, r2, r3;
                LDSM4(r0, r1, r2, r3, ad);
                bfr[h][pr * 2][ks][0] = r0; bfr[h][pr * 2 + 1][ks][0] = r1;
                bfr[h][pr * 2][ks][1] = r2; bfr[h][pr * 2 + 1][ks][1] = r3;
            }
    __syncthreads();

    for (int t = 0; t < TP; t++) {
        const int p = t & 1;
        // per-warp wait: lanes 0,1 poll this warp's two producer flags (target 8t)
        if (t > 0) {
            if (lane < 2) {
                const unsigned target = (unsigned)(t << 3);
                while (ld_acq(myflag) < target) {}
            }
            __syncwarp();
        }

        // warp-local state chunk load (fp16, 2KB) + pre[t+1] prefetch
        const __half* s_g = g_sf16[p];
        const size_t gb2 = (size_t)b0 * 512 + (size_t)(wid << 6);
#pragma unroll
        for (int i = 0; i < 4; i++) {
            const int unit = lane + (i << 5);
            const int row = unit >> 3, col = unit & 7;
            cpa16(schunk + SWZ((uint32_t)(row * 128 + col * 16)),
                  s_g + gb2 + (size_t)row * 512 + col * 8);
        }
        if (t + 1 < TP && tid < 128) {
            const int row = tid >> 3, col = (tid & 7) << 2;
            cpa16(preb + (uint32_t)(((t + 1) & 1) << 11) + (uint32_t)(row * 128 + col * 4),
                  &C[((size_t)(b0 + row) * TP + (t + 1)) * UU + n0 + col]);
        }
        CP_COMMIT();
        CP_WAIT(0);

        float acc[4][4];
#pragma unroll
        for (int nf = 0; nf < 4; nf++)
#pragma unroll
            for (int q = 0; q < 4; q++) acc[nf][q] = 0.0f;

#pragma unroll
        for (int ks = 0; ks < 4; ks++) {
            uint32_t a[4];
            const int row = radd + rlow;
            const int col = ks * 2 + cadd;
            LDSM4(a[0], a[1], a[2], a[3],
                  schunk + SWZ((uint32_t)(row * 128 + col * 16)));
#pragma unroll
            for (int nf = 0; nf < 4; nf++) {
                mma_f16(acc[nf], a, bfr[0][nf][ks]);
                mma_f16(acc[nf], a, bfr[1][nf][ks]);
            }
        }

        // stash partials into buf slot p (per-warp disjoint)
        float* bufp = (float*)(smem + 65536 + (p << 14));
#pragma unroll
        for (int nf = 0; nf < 4; nf++) {
            const int row = lane >> 2;
            const int col = nf * 8 + ((lane & 3) << 1);
            float* bp = bufp + (wid << 9) + row * 32 + col;
            bp[0] = acc[nf][0]; bp[1] = acc[nf][1];
            bp[256] = acc[nf][2]; bp[257] = acc[nf][3];
        }
        __syncthreads();   // the ONE block barrier per step

        const float2* b2 = (const float2*)bufp;
        float2 s = b2[tid];
#pragma unroll
        for (int w = 1; w < 8; w++) {
            const float2 v = b2[(w << 8) + tid];
            s.x += v.x; s.y += v.y;
        }

        const float2 pre = *(const float2*)(smem + 98304 + (p << 11) +
                                            ((e_b * 32 + e_u) << 2));
        const float o[2] = {pre.x + s.x, pre.y + s.y};
        float nn[2], st[2];
#pragma unroll
        for (int j = 0; j < 2; j++) {
            const float n = 1.0f / (1.0f + __expf(-3.0f * o[j]));
            nn[j] = n;
            st[j] = o[j] / (1.0f + __expf(2.0f * n - 1.0f));
        }
        *(__half2*)&g_sf16[p ^ 1][srow] = __floats2half2_rn(st[0], st[1]);
        __syncwarp();
        if (lane == 0) red_rel(relflag);   // per-warp release (+1; step total 8)

        const size_t crow = ((size_t)bglob * TP + t) * UU + n0 + e_u;
        *(float2*)&C[crow] = make_float2(nn[0], nn[1]);
    }
}

extern "C" void kernel_launch(void* const* d_in, const int* in_sizes, int n_in,
                              void* d_out, int out_size) {
    const float* x    = (const float*)d_in[0];
    const float* pw   = (const float*)d_in[1];
    const float* pb   = (const float*)d_in[2];
    const float* Kw   = (const float*)d_in[3];
    const float* Rm   = (const float*)d_in[4];
    const float* bias = (const float*)d_in[5];
    float* out = (float*)d_out;

    cudaFuncSetAttribute(gemm_mma_kernel,
                         cudaFuncAttributeMaxDynamicSharedMemorySize, GEMM_SMEM);
    cudaFuncSetAttribute(rnn_tc_kernel,
                         cudaFuncAttributeMaxDynamicSharedMemorySize, RNN_SMEM);

    init_kernel<<<(BB * UU) / 256, 256>>>();
    prep_kernel<<<2048, 256>>>(Kw, Rm);
    conv_kernel<<<dim3(16, BB, 4), 256>>>(x, pw, pb);
    gemm_mma_kernel<<<dim3(UU / 128, MTOT / 128), 256, GEMM_SMEM>>>(bias, out);
    rnn_tc_kernel<<<dim3(16, 16), 256, RNN_SMEM>>>(out);
}

// round 16
// speedup vs baseline: 1.2217x; 1.0941x over previous
#include <cuda_runtime.h>
#include <cuda_bf16.h>
#include <cuda_fp16.h>
#include <cstdint>

#define BB 256
#define TT 1024
#define WW 512
#define UU 512
#define PP 16
#define TP (TT - PP + 1)
#define MTOT (BB * TP)

__device__ __align__(16) __half g_A16[(size_t)MTOT * WW];   // syn fp16 [b][t][w]
__device__ __align__(16) __half g_Bh16[WW * UU];            // K^T hi [n][k] fp16
__device__ __align__(16) __half g_Bl16[WW * UU];            // K^T lo [n][k] fp16
__device__ __align__(16) __half g_Rh16[UU * UU];            // R^T hi [n][k] fp16
__device__ __align__(16) __half g_Rl16[UU * UU];            // R^T lo [n][k] fp16
__device__ __align__(16) __half g_sf16[2][BB * UU];         // state fp16 [parity]
__device__ unsigned g_flags[16][16 * 32];  // [batch-group][u-tile], 128B padded

typedef unsigned long long u64;
__device__ __forceinline__ unsigned ld_acq(const unsigned* p) {
    unsigned v;
    asm volatile("ld.global.acquire.gpu.u32 %0, [%1];" : "=r"(v) : "l"(p) : "memory");
    return v;
}
__device__ __forceinline__ void red_rel(unsigned* p) {
    asm volatile("red.release.gpu.global.add.u32 [%0], 1;" :: "l"(p) : "memory");
}
__device__ __forceinline__ uint32_t smem_u32(const void* p) {
    uint32_t a;
    asm("{ .reg .u64 t; cvta.to.shared.u64 t, %1; cvt.u32.u64 %0, t; }" : "=r"(a) : "l"(p));
    return a;
}
__device__ __forceinline__ void cpa16(uint32_t s, const void* g) {
    asm volatile("cp.async.cg.shared.global [%0], [%1], 16;" :: "r"(s), "l"(g) : "memory");
}
#define CP_COMMIT() asm volatile("cp.async.commit_group;" ::: "memory")
#define CP_WAIT(n)  asm volatile("cp.async.wait_group %0;" :: "n"(n) : "memory")
#define SWZ(x) ((x) ^ (((x) >> 3) & 0x70))
#define LDSM4(r0, r1, r2, r3, a) \
    asm volatile("ldmatrix.sync.aligned.m8n8.x4.shared.b16 {%0,%1,%2,%3}, [%4];" \
                 : "=r"(r0), "=r"(r1), "=r"(r2), "=r"(r3) : "r"(a))
__device__ __forceinline__ void mma_f16(float* c, const uint32_t* a, const uint32_t* b) {
    asm volatile(
        "mma.sync.aligned.m16n8k16.row.col.f32.f16.f16.f32 "
        "{%0,%1,%2,%3}, {%4,%5,%6,%7}, {%8,%9}, {%0,%1,%2,%3};"
        : "+f"(c[0]), "+f"(c[1]), "+f"(c[2]), "+f"(c[3])
        : "r"(a[0]), "r"(a[1]), "r"(a[2]), "r"(a[3]), "r"(b[0]), "r"(b[1]));
}

// ---- init ----
__global__ void init_kernel() {
    const int i = blockIdx.x * 256 + threadIdx.x;
    if (i < BB * UU) g_sf16[0][i] = __float2half(0.0f);
    if (i < 16 * 16 * 32) ((unsigned*)g_flags)[i] = 0u;
}

// ---- prep: transpose + fp16 hi/lo split of K and R ----
__global__ void prep_kernel(const float* __restrict__ Kw, const float* __restrict__ Rm) {
    const int gb = blockIdx.x;
    const int i = (gb & 1023) * 256 + threadIdx.x;
    const int n = i >> 9, k = i & 511;
    if (gb < 1024) {
        const float v = __ldg(&Kw[(size_t)k * UU + n]);
        const __half h = __float2half(v);
        g_Bh16[i] = h;
        g_Bl16[i] = __float2half(v - __half2float(h));
    } else {
        const float v = __ldg(&Rm[(size_t)k * UU + n]);
        const __half h = __float2half(v);
        g_Rh16[i] = h;
        g_Rl16[i] = __float2half(v - __half2float(h));
    }
}

// ---- 1) conv with register sliding window, fp16 output ----
__global__ __launch_bounds__(256) void conv_kernel(const float* __restrict__ x,
                                                   const float* __restrict__ pw,
                                                   const float* __restrict__ pb) {
    const int tc = blockIdx.x;
    const int b  = blockIdx.y;
    const int wc = blockIdx.z;
    const int tid = threadIdx.x;
    const int wp = tid & 63;
    const int tg = tid >> 6;
    const int w = wc * 128 + wp * 2;
    const int tstart = tc * 64 + tg * 16;

    float cf[PP];
#pragma unroll
    for (int k = 0; k < PP; k++) cf[k] = __ldg(&pw[k]);
    const float bias = __ldg(&pb[0]);

    const float2* xp = (const float2*)(x + (size_t)b * TT * WW + w);
    float2 win[16];
#pragma unroll
    for (int i = 0; i < 16; i++)
        win[i] = xp[(size_t)(tstart + i) * (WW / 2)];

#pragma unroll
    for (int j = 0; j < 16; j++) {
        const int t = tstart + j;
        if (t < TP) {
            float ox = bias, oy = bias;
#pragma unroll
            for (int k = 0; k < PP; k++) {
                const float2 v = win[(j + k) & 15];
                ox += cf[k] * v.x;
                oy += cf[k] * v.y;
            }
            const size_t idx = ((size_t)b * TP + t) * WW + w;
            *(__half2*)&g_A16[idx] = __floats2half2_rn(ox, oy);
            const int tl = t + PP;
            if (tl < TT) win[j & 15] = xp[(size_t)tl * (WW / 2)];
        }
    }
}

// ---- 2) pre = syn @ K + bias, fp16x2 mma.sync, 3-stage ----
#define STAGE_BYTES 49152
#define GEMM_SMEM (3 * STAGE_BYTES)
__global__ __launch_bounds__(256, 1) void gemm_mma_kernel(const float* __restrict__ bias,
                                                          float* __restrict__ C) {
    extern __shared__ __align__(1024) char smem[];
    const uint32_t sb = smem_u32(smem);
    const int tid = threadIdx.x, lane = tid & 31, wid = tid >> 5;
    const int warp_m = wid & 3, warp_n = wid >> 2;
    const size_t m0 = (size_t)blockIdx.y * 128;
    const int n0 = blockIdx.x * 128;

    float acc[2][8][4];
#pragma unroll
    for (int i = 0; i < 2; i++)
#pragma unroll
        for (int j = 0; j < 8; j++)
#pragma unroll
            for (int q = 0; q < 4; q++) acc[i][j][q] = 0.0f;

    const int lcol = tid & 7, lrow = tid >> 3;
    auto load_stage = [&](int st, int k0) {
        const uint32_t sst = sb + (uint32_t)(st * STAGE_BYTES);
#pragma unroll
        for (int buf = 0; buf < 3; buf++) {
            const __half* src = (buf == 0) ? g_A16 : (buf == 1) ? g_Bh16 : g_Bl16;
            const size_t rbase = (buf == 0) ? m0 : (size_t)n0;
            const uint32_t sbuf = sst + buf * 16384;
#pragma unroll
            for (int i = 0; i < 4; i++) {
                const int row = lrow + 32 * i;
                cpa16(sbuf + SWZ((uint32_t)(row * 128 + lcol * 16)),
                      src + (rbase + row) * 512 + k0 + lcol * 8);
            }
        }
    };

    load_stage(0, 0);
    CP_COMMIT();
    load_stage(1, 64);
    CP_COMMIT();

    const int rsel = lane >> 3, rlow = lane & 7;
    const int radd = (rsel & 1) << 3, cadd = rsel >> 1;

    for (int c = 0; c < 8; c++) {
        if (c + 2 < 8) {
            load_stage((c + 2) % 3, (c + 2) << 6);
            CP_COMMIT();
        }
        if (c < 6) { CP_WAIT(2); } else if (c == 6) { CP_WAIT(1); } else { CP_WAIT(0); }
        __syncthreads();

        const uint32_t ss = sb + (uint32_t)((c % 3) * STAGE_BYTES);
#pragma unroll
        for (int ks = 0; ks < 4; ks++) {
            uint32_t a[2][4];
#pragma unroll
            for (int mf = 0; mf < 2; mf++) {
                const int row = warp_m * 32 + mf * 16 + radd + rlow;
                const int col = ks * 2 + cadd;
                const uint32_t ad = ss + SWZ((uint32_t)(row * 128 + col * 16));
                LDSM4(a[mf][0], a[mf][1], a[mf][2], a[mf][3], ad);
            }
            uint32_t b[2][8][2];
#pragma unroll
            for (int h = 0; h < 2; h++)
#pragma unroll
                for (int pr = 0; pr < 4; pr++) {
                    const int row = warp_n * 64 + pr * 16 + radd + rlow;
                    const int col = ks * 2 + cadd;
                    const uint32_t ad = ss + 16384 + h * 16384 +
                                        SWZ((uint32_t)(row * 128 + col * 16));
                    uint32_t r0, r1, r2, r3;
                    LDSM4(r0, r1, r2, r3, ad);
                    b[h][pr * 2][0] = r0; b[h][pr * 2 + 1][0] = r1;
                    b[h][pr * 2][1] = r2; b[h][pr * 2 + 1][1] = r3;
                }
#pragma unroll
            for (int mf = 0; mf < 2; mf++)
#pragma unroll
                for (int nf = 0; nf < 8; nf++) {
                    mma_f16(acc[mf][nf], a[mf], b[0][nf]);
                    mma_f16(acc[mf][nf], a[mf], b[1][nf]);
                }
        }
        __syncthreads();
    }

#pragma unroll
    for (int mf = 0; mf < 2; mf++) {
        const int row = warp_m * 32 + mf * 16 + (lane >> 2);
        const size_t gr0 = (m0 + row) * 512;
        const size_t gr1 = (m0 + row + 8) * 512;
#pragma unroll
        for (int nf = 0; nf < 8; nf++) {
            const int col = n0 + warp_n * 64 + nf * 8 + (lane & 3) * 2;
            const float2 bv = *(const float2*)&bias[col];
            *(float2*)&C[gr0 + col] =
                make_float2(acc[mf][nf][0] + bv.x, acc[mf][nf][1] + bv.y);
            *(float2*)&C[gr1 + col] =
                make_float2(acc[mf][nf][2] + bv.x, acc[mf][nf][3] + bv.y);
        }
    }
}

// ---- 3) persistent recurrence (R15, frozen) ----
#define RNN_SMEM 102400
__global__ __launch_bounds__(256, 2) void rnn_tc_kernel(float* __restrict__ C) {
    extern __shared__ __align__(1024) char smem[];
    const uint32_t sb = smem_u32(smem);
    const uint32_t preb = sb + 98304;

    const int tid = threadIdx.x, lane = tid & 31, wid = tid >> 5;
    const int bt = blockIdx.x, ut = blockIdx.y;
    const int n0 = ut << 5, b0 = bt << 4;

    const int rsel = lane >> 3, rlow = lane & 7;
    const int radd = (rsel & 1) << 3, cadd = rsel >> 1;
    const uint32_t rchunk = sb + (uint32_t)(wid << 12);
    const uint32_t schunk = sb + (uint32_t)(wid << 11);

    const int e_b = tid >> 4;
    const int e_u = (tid & 15) << 1;
    const int bglob = b0 + e_b;
    const size_t srow = (size_t)bglob * UU + n0 + e_u;
    const unsigned* myflag = (lane < 2) ? &g_flags[bt][((wid << 1) | lane) * 32] : 0;
    unsigned* const relflag = &g_flags[bt][ut * 32];

#pragma unroll
    for (int i = 0; i < 8; i++) {
        const int unit = tid + (i << 8);
        const int chunk = unit >> 8, rem = unit & 255;
        const int row = rem >> 3, col = rem & 7;
        const uint32_t soff = (uint32_t)(chunk << 12) + SWZ((uint32_t)(row * 128 + col * 16));
        const size_t gidx = (size_t)(n0 + row) * 512 + chunk * 64 + col * 8;
        cpa16(sb + soff, g_Rh16 + gidx);
        cpa16(sb + 32768 + soff, g_Rl16 + gidx);
    }
    if (tid < 128) {
        const int row = tid >> 3, col = (tid & 7) << 2;
        cpa16(preb + (uint32_t)(row * 128 + col * 4),
              &C[((size_t)(b0 + row) * TP) * UU + n0 + col]);
    }
    CP_COMMIT();
    CP_WAIT(0);
    __syncthreads();

    uint32_t bfr[2][4][4][2];
#pragma unroll
    for (int h = 0; h < 2; h++)
#pragma unroll
        for (int pr = 0; pr < 2; pr++)
#pragma unroll
            for (int ks = 0; ks < 4; ks++) {
                const int row = pr * 16 + radd + rlow;
                const int col = ks * 2 + cadd;
                const uint32_t ad = rchunk + h * 32768 +
                                    SWZ((uint32_t)(row * 128 + col * 16));
                uint32_t r0, r1, r2, r3;
                LDSM4(r0, r1, r2, r3, ad);
                bfr[h][pr * 2][ks][0] = r0; bfr[h][pr * 2 + 1][ks][0] = r1;
                bfr[h][pr * 2][ks][1] = r2; bfr[h][pr * 2 + 1][ks][1] = r3;
            }
    __syncthreads();

    for (int t = 0; t < TP; t++) {
        const int p = t & 1;
        if (t > 0) {
            if (lane < 2) {
                const unsigned target = (unsigned)(t << 3);
                while (ld_acq(myflag) < target) {}
            }
            __syncwarp();
        }

        const __half* s_g = g_sf16[p];
        const size_t gb2 = (size_t)b0 * 512 + (size_t)(wid << 6);
#pragma unroll
        for (int i = 0; i < 4; i++) {
            const int unit = lane + (i << 5);
            const int row = unit >> 3, col = unit & 7;
            cpa16(schunk + SWZ((uint32_t)(row * 128 + col * 16)),
                  s_g + gb2 + (size_t)row * 512 + col * 8);
        }
        if (t + 1 < TP && tid < 128) {
            const int row = tid >> 3, col = (tid & 7) << 2;
            cpa16(preb + (uint32_t)(((t + 1) & 1) << 11) + (uint32_t)(row * 128 + col * 4),
                  &C[((size_t)(b0 + row) * TP + (t + 1)) * UU + n0 + col]);
        }
        CP_COMMIT();
        CP_WAIT(0);

        float acc[4][4];
#pragma unroll
        for (int nf = 0; nf < 4; nf++)
#pragma unroll
            for (int q = 0; q < 4; q++) acc[nf][q] = 0.0f;

#pragma unroll
        for (int ks = 0; ks < 4; ks++) {
            uint32_t a[4];
            const int row = radd + rlow;
            const int col = ks * 2 + cadd;
            LDSM4(a[0], a[1], a[2], a[3],
                  schunk + SWZ((uint32_t)(row * 128 + col * 16)));
#pragma unroll
            for (int nf = 0; nf < 4; nf++) {
                mma_f16(acc[nf], a, bfr[0][nf][ks]);
                mma_f16(acc[nf], a, bfr[1][nf][ks]);
            }
        }

        float* bufp = (float*)(smem + 65536 + (p << 14));
#pragma unroll
        for (int nf = 0; nf < 4; nf++) {
            const int row = lane >> 2;
            const int col = nf * 8 + ((lane & 3) << 1);
            float* bp = bufp + (wid << 9) + row * 32 + col;
            bp[0] = acc[nf][0]; bp[1] = acc[nf][1];
            bp[256] = acc[nf][2]; bp[257] = acc[nf][3];
        }
        __syncthreads();

        const float2* b2 = (const float2*)bufp;
        float2 s = b2[tid];
#pragma unroll
        for (int w = 1; w < 8; w++) {
            const float2 v = b2[(w << 8) + tid];
            s.x += v.x; s.y += v.y;
        }

        const float2 pre = *(const float2*)(smem + 98304 + (p << 11) +
                                            ((e_b * 32 + e_u) << 2));
        const float o[2] = {pre.x + s.x, pre.y + s.y};
        float nn[2], st[2];
#pragma unroll
        for (int j = 0; j < 2; j++) {
            const float n = 1.0f / (1.0f + __expf(-3.0f * o[j]));
            nn[j] = n;
            st[j] = o[j] / (1.0f + __expf(2.0f * n - 1.0f));
        }
        *(__half2*)&g_sf16[p ^ 1][srow] = __floats2half2_rn(st[0], st[1]);
        __syncwarp();
        if (lane == 0) red_rel(relflag);

        const size_t crow = ((size_t)bglob * TP + t) * UU + n0 + e_u;
        *(float2*)&C[crow] = make_float2(nn[0], nn[1]);
    }
}

extern "C" void kernel_launch(void* const* d_in, const int* in_sizes, int n_in,
                              void* d_out, int out_size) {
    const float* x    = (const float*)d_in[0];
    const float* pw   = (const float*)d_in[1];
    const float* pb   = (const float*)d_in[2];
    const float* Kw   = (const float*)d_in[3];
    const float* Rm   = (const float*)d_in[4];
    const float* bias = (const float*)d_in[5];
    float* out = (float*)d_out;

    cudaFuncSetAttribute(gemm_mma_kernel,
                         cudaFuncAttributeMaxDynamicSharedMemorySize, GEMM_SMEM);
    cudaFuncSetAttribute(rnn_tc_kernel,
                         cudaFuncAttributeMaxDynamicSharedMemorySize, RNN_SMEM);

    init_kernel<<<(BB * UU) / 256, 256>>>();
    prep_kernel<<<2048, 256>>>(Kw, Rm);
    conv_kernel<<<dim3(16, BB, 4), 256>>>(x, pw, pb);
    gemm_mma_kernel<<<dim3(UU / 128, MTOT / 128), 256, GEMM_SMEM>>>(bias, out);
    rnn_tc_kernel<<<dim3(16, 16), 256, RNN_SMEM>>>(out);
}

// round 17
// speedup vs baseline: 1.3179x; 1.0787x over previous
#include <cuda_runtime.h>
#include <cuda_bf16.h>
#include <cuda_fp16.h>
#include <cstdint>

#define BB 256
#define TT 1024
#define WW 512
#define UU 512
#define PP 16
#define TP (TT - PP + 1)
#define MTOT (BB * TP)

__device__ __align__(16) __half g_A16[(size_t)MTOT * WW];   // syn fp16 [b][t][w]
__device__ __align__(16) __half g_B16[WW * UU];             // K^T fp16 [n][k]
__device__ __align__(16) __half g_Rh16[UU * UU];            // R^T hi [n][k] fp16
__device__ __align__(16) __half g_Rl16[UU * UU];            // R^T lo [n][k] fp16
__device__ __align__(16) __half g_sf16[2][BB * UU];         // state fp16 [parity]
__device__ unsigned g_flags[16][16 * 32];  // [batch-group][u-tile], 128B padded

typedef unsigned long long u64;
__device__ __forceinline__ unsigned ld_acq(const unsigned* p) {
    unsigned v;
    asm volatile("ld.global.acquire.gpu.u32 %0, [%1];" : "=r"(v) : "l"(p) : "memory");
    return v;
}
__device__ __forceinline__ void red_rel(unsigned* p) {
    asm volatile("red.release.gpu.global.add.u32 [%0], 1;" :: "l"(p) : "memory");
}
__device__ __forceinline__ uint32_t smem_u32(const void* p) {
    uint32_t a;
    asm("{ .reg .u64 t; cvta.to.shared.u64 t, %1; cvt.u32.u64 %0, t; }" : "=r"(a) : "l"(p));
    return a;
}
__device__ __forceinline__ void cpa16(uint32_t s, const void* g) {
    asm volatile("cp.async.cg.shared.global [%0], [%1], 16;" :: "r"(s), "l"(g) : "memory");
}
#define CP_COMMIT() asm volatile("cp.async.commit_group;" ::: "memory")
#define CP_WAIT(n)  asm volatile("cp.async.wait_group %0;" :: "n"(n) : "memory")
#define SWZ(x) ((x) ^ (((x) >> 3) & 0x70))
#define LDSM4(r0, r1, r2, r3, a) \
    asm volatile("ldmatrix.sync.aligned.m8n8.x4.shared.b16 {%0,%1,%2,%3}, [%4];" \
                 : "=r"(r0), "=r"(r1), "=r"(r2), "=r"(r3) : "r"(a))
__device__ __forceinline__ void mma_f16(float* c, const uint32_t* a, const uint32_t* b) {
    asm volatile(
        "mma.sync.aligned.m16n8k16.row.col.f32.f16.f16.f32 "
        "{%0,%1,%2,%3}, {%4,%5,%6,%7}, {%8,%9}, {%0,%1,%2,%3};"
        : "+f"(c[0]), "+f"(c[1]), "+f"(c[2]), "+f"(c[3])
        : "r"(a[0]), "r"(a[1]), "r"(a[2]), "r"(a[3]), "r"(b[0]), "r"(b[1]));
}

// ---- init ----
__global__ void init_kernel() {
    const int i = blockIdx.x * 256 + threadIdx.x;
    if (i < BB * UU) g_sf16[0][i] = __float2half(0.0f);
    if (i < 16 * 16 * 32) ((unsigned*)g_flags)[i] = 0u;
}

// ---- prep: transpose; K single fp16, R fp16 hi/lo ----
__global__ void prep_kernel(const float* __restrict__ Kw, const float* __restrict__ Rm) {
    const int gb = blockIdx.x;
    const int i = (gb & 1023) * 256 + threadIdx.x;
    const int n = i >> 9, k = i & 511;
    if (gb < 1024) {
        g_B16[i] = __float2half(__ldg(&Kw[(size_t)k * UU + n]));
    } else {
        const float v = __ldg(&Rm[(size_t)k * UU + n]);
        const __half h = __float2half(v);
        g_Rh16[i] = h;
        g_Rl16[i] = __float2half(v - __half2float(h));
    }
}

// ---- 1) conv with register sliding window, fp16 output ----
__global__ __launch_bounds__(256) void conv_kernel(const float* __restrict__ x,
                                                   const float* __restrict__ pw,
                                                   const float* __restrict__ pb) {
    const int tc = blockIdx.x;
    const int b  = blockIdx.y;
    const int wc = blockIdx.z;
    const int tid = threadIdx.x;
    const int wp = tid & 63;
    const int tg = tid >> 6;
    const int w = wc * 128 + wp * 2;
    const int tstart = tc * 64 + tg * 16;

    float cf[PP];
#pragma unroll
    for (int k = 0; k < PP; k++) cf[k] = __ldg(&pw[k]);
    const float bias = __ldg(&pb[0]);

    const float2* xp = (const float2*)(x + (size_t)b * TT * WW + w);
    float2 win[16];
#pragma unroll
    for (int i = 0; i < 16; i++)
        win[i] = xp[(size_t)(tstart + i) * (WW / 2)];

#pragma unroll
    for (int j = 0; j < 16; j++) {
        const int t = tstart + j;
        if (t < TP) {
            float ox = bias, oy = bias;
#pragma unroll
            for (int k = 0; k < PP; k++) {
                const float2 v = win[(j + k) & 15];
                ox += cf[k] * v.x;
                oy += cf[k] * v.y;
            }
            const size_t idx = ((size_t)b * TP + t) * WW + w;
            *(__half2*)&g_A16[idx] = __floats2half2_rn(ox, oy);
            const int tl = t + PP;
            if (tl < TT) win[j & 15] = xp[(size_t)tl * (WW / 2)];
        }
    }
}

// ---- 2) pre = syn @ K + bias, fp16 single-term mma.sync, 3-stage ----
#define STAGE_BYTES 32768
#define GEMM_SMEM (3 * STAGE_BYTES)
__global__ __launch_bounds__(256, 1) void gemm_mma_kernel(const float* __restrict__ bias,
                                                          float* __restrict__ C) {
    extern __shared__ __align__(1024) char smem[];
    const uint32_t sb = smem_u32(smem);
    const int tid = threadIdx.x, lane = tid & 31, wid = tid >> 5;
    const int warp_m = wid & 3, warp_n = wid >> 2;
    const size_t m0 = (size_t)blockIdx.y * 128;
    const int n0 = blockIdx.x * 128;

    float acc[2][8][4];
#pragma unroll
    for (int i = 0; i < 2; i++)
#pragma unroll
        for (int j = 0; j < 8; j++)
#pragma unroll
            for (int q = 0; q < 4; q++) acc[i][j][q] = 0.0f;

    const int lcol = tid & 7, lrow = tid >> 3;
    auto load_stage = [&](int st, int k0) {
        const uint32_t sst = sb + (uint32_t)(st * STAGE_BYTES);
#pragma unroll
        for (int buf = 0; buf < 2; buf++) {
            const __half* src = (buf == 0) ? g_A16 : g_B16;
            const size_t rbase = (buf == 0) ? m0 : (size_t)n0;
            const uint32_t sbuf = sst + buf * 16384;
#pragma unroll
            for (int i = 0; i < 4; i++) {
                const int row = lrow + 32 * i;
                cpa16(sbuf + SWZ((uint32_t)(row * 128 + lcol * 16)),
                      src + (rbase + row) * 512 + k0 + lcol * 8);
            }
        }
    };

    load_stage(0, 0);
    CP_COMMIT();
    load_stage(1, 64);
    CP_COMMIT();

    const int rsel = lane >> 3, rlow = lane & 7;
    const int radd = (rsel & 1) << 3, cadd = rsel >> 1;

    for (int c = 0; c < 8; c++) {
        if (c + 2 < 8) {
            load_stage((c + 2) % 3, (c + 2) << 6);
            CP_COMMIT();
        }
        if (c < 6) { CP_WAIT(2); } else if (c == 6) { CP_WAIT(1); } else { CP_WAIT(0); }
        __syncthreads();

        const uint32_t ss = sb + (uint32_t)((c % 3) * STAGE_BYTES);
#pragma unroll
        for (int ks = 0; ks < 4; ks++) {
            uint32_t a[2][4];
#pragma unroll
            for (int mf = 0; mf < 2; mf++) {
                const int row = warp_m * 32 + mf * 16 + radd + rlow;
                const int col = ks * 2 + cadd;
                const uint32_t ad = ss + SWZ((uint32_t)(row * 128 + col * 16));
                LDSM4(a[mf][0], a[mf][1], a[mf][2], a[mf][3], ad);
            }
            uint32_t b[8][2];
#pragma unroll
            for (int pr = 0; pr < 4; pr++) {
                const int row = warp_n * 64 + pr * 16 + radd + rlow;
                const int col = ks * 2 + cadd;
                const uint32_t ad = ss + 16384 + SWZ((uint32_t)(row * 128 + col * 16));
                uint32_t r0, r1, r2, r3;
                LDSM4(r0, r1, r2, r3, ad);
                b[pr * 2][0] = r0; b[pr * 2 + 1][0] = r1;
                b[pr * 2][1] = r2; b[pr * 2 + 1][1] = r3;
            }
#pragma unroll
            for (int mf = 0; mf < 2; mf++)
#pragma unroll
                for (int nf = 0; nf < 8; nf++)
                    mma_f16(acc[mf][nf], a[mf], b[nf]);
        }
        __syncthreads();
    }

#pragma unroll
    for (int mf = 0; mf < 2; mf++) {
        const int row = warp_m * 32 + mf * 16 + (lane >> 2);
        const size_t gr0 = (m0 + row) * 512;
        const size_t gr1 = (m0 + row + 8) * 512;
#pragma unroll
        for (int nf = 0; nf < 8; nf++) {
            const int col = n0 + warp_n * 64 + nf * 8 + (lane & 3) * 2;
            const float2 bv = *(const float2*)&bias[col];
            *(float2*)&C[gr0 + col] =
                make_float2(acc[mf][nf][0] + bv.x, acc[mf][nf][1] + bv.y);
            *(float2*)&C[gr1 + col] =
                make_float2(acc[mf][nf][2] + bv.x, acc[mf][nf][3] + bv.y);
        }
    }
}

// ---- 3) persistent recurrence (R15, frozen) ----
#define RNN_SMEM 102400
__global__ __launch_bounds__(256, 2) void rnn_tc_kernel(float* __restrict__ C) {
    extern __shared__ __align__(1024) char smem[];
    const uint32_t sb = smem_u32(smem);
    const uint32_t preb = sb + 98304;

    const int tid = threadIdx.x, lane = tid & 31, wid = tid >> 5;
    const int bt = blockIdx.x, ut = blockIdx.y;
    const int n0 = ut << 5, b0 = bt << 4;

    const int rsel = lane >> 3, rlow = lane & 7;
    const int radd = (rsel & 1) << 3, cadd = rsel >> 1;
    const uint32_t rchunk = sb + (uint32_t)(wid << 12);
    const uint32_t schunk = sb + (uint32_t)(wid << 11);

    const int e_b = tid >> 4;
    const int e_u = (tid & 15) << 1;
    const int bglob = b0 + e_b;
    const size_t srow = (size_t)bglob * UU + n0 + e_u;
    const unsigned* myflag = (lane < 2) ? &g_flags[bt][((wid << 1) | lane) * 32] : 0;
    unsigned* const relflag = &g_flags[bt][ut * 32];

#pragma unroll
    for (int i = 0; i < 8; i++) {
        const int unit = tid + (i << 8);
        const int chunk = unit >> 8, rem = unit & 255;
        const int row = rem >> 3, col = rem & 7;
        const uint32_t soff = (uint32_t)(chunk << 12) + SWZ((uint32_t)(row * 128 + col * 16));
        const size_t gidx = (size_t)(n0 + row) * 512 + chunk * 64 + col * 8;
        cpa16(sb + soff, g_Rh16 + gidx);
        cpa16(sb + 32768 + soff, g_Rl16 + gidx);
    }
    if (tid < 128) {
        const int row = tid >> 3, col = (tid & 7) << 2;
        cpa16(preb + (uint32_t)(row * 128 + col * 4),
              &C[((size_t)(b0 + row) * TP) * UU + n0 + col]);
    }
    CP_COMMIT();
    CP_WAIT(0);
    __syncthreads();

    uint32_t bfr[2][4][4][2];
#pragma unroll
    for (int h = 0; h < 2; h++)
#pragma unroll
        for (int pr = 0; pr < 2; pr++)
#pragma unroll
            for (int ks = 0; ks < 4; ks++) {
                const int row = pr * 16 + radd + rlow;
                const int col = ks * 2 + cadd;
                const uint32_t ad = rchunk + h * 32768 +
                                    SWZ((uint32_t)(row * 128 + col * 16));
                uint32_t r0, r1, r2, r3;
                LDSM4(r0, r1, r2, r3, ad);
                bfr[h][pr * 2][ks][0] = r0; bfr[h][pr * 2 + 1][ks][0] = r1;
                bfr[h][pr * 2][ks][1] = r2; bfr[h][pr * 2 + 1][ks][1] = r3;
            }
    __syncthreads();

    for (int t = 0; t < TP; t++) {
        const int p = t & 1;
        if (t > 0) {
            if (lane < 2) {
                const unsigned target = (unsigned)(t << 3);
                while (ld_acq(myflag) < target) {}
            }
            __syncwarp();
        }

        const __half* s_g = g_sf16[p];
        const size_t gb2 = (size_t)b0 * 512 + (size_t)(wid << 6);
#pragma unroll
        for (int i = 0; i < 4; i++) {
            const int unit = lane + (i << 5);
            const int row = unit >> 3, col = unit & 7;
            cpa16(schunk + SWZ((uint32_t)(row * 128 + col * 16)),
                  s_g + gb2 + (size_t)row * 512 + col * 8);
        }
        if (t + 1 < TP && tid < 128) {
            const int row = tid >> 3, col = (tid & 7) << 2;
            cpa16(preb + (uint32_t)(((t + 1) & 1) << 11) + (uint32_t)(row * 128 + col * 4),
                  &C[((size_t)(b0 + row) * TP + (t + 1)) * UU + n0 + col]);
        }
        CP_COMMIT();
        CP_WAIT(0);

        float acc[4][4];
#pragma unroll
        for (int nf = 0; nf < 4; nf++)
#pragma unroll
            for (int q = 0; q < 4; q++) acc[nf][q] = 0.0f;

#pragma unroll
        for (int ks = 0; ks < 4; ks++) {
            uint32_t a[4];
            const int row = radd + rlow;
            const int col = ks * 2 + cadd;
            LDSM4(a[0], a[1], a[2], a[3],
                  schunk + SWZ((uint32_t)(row * 128 + col * 16)));
#pragma unroll
            for (int nf = 0; nf < 4; nf++) {
                mma_f16(acc[nf], a, bfr[0][nf][ks]);
                mma_f16(acc[nf], a, bfr[1][nf][ks]);
            }
        }

        float* bufp = (float*)(smem + 65536 + (p << 14));
#pragma unroll
        for (int nf = 0; nf < 4; nf++) {
            const int row = lane >> 2;
            const int col = nf * 8 + ((lane & 3) << 1);
            float* bp = bufp + (wid << 9) + row * 32 + col;
            bp[0] = acc[nf][0]; bp[1] = acc[nf][1];
            bp[256] = acc[nf][2]; bp[257] = acc[nf][3];
        }
        __syncthreads();

        const float2* b2 = (const float2*)bufp;
        float2 s = b2[tid];
#pragma unroll
        for (int w = 1; w < 8; w++) {
            const float2 v = b2[(w << 8) + tid];
            s.x += v.x; s.y += v.y;
        }

        const float2 pre = *(const float2*)(smem + 98304 + (p << 11) +
                                            ((e_b * 32 + e_u) << 2));
        const float o[2] = {pre.x + s.x, pre.y + s.y};
        float nn[2], st[2];
#pragma unroll
        for (int j = 0; j < 2; j++) {
            const float n = 1.0f / (1.0f + __expf(-3.0f * o[j]));
            nn[j] = n;
            st[j] = o[j] / (1.0f + __expf(2.0f * n - 1.0f));
        }
        *(__half2*)&g_sf16[p ^ 1][srow] = __floats2half2_rn(st[0], st[1]);
        __syncwarp();
        if (lane == 0) red_rel(relflag);

        const size_t crow = ((size_t)bglob * TP + t) * UU + n0 + e_u;
        *(float2*)&C[crow] = make_float2(nn[0], nn[1]);
    }
}

extern "C" void kernel_launch(void* const* d_in, const int* in_sizes, int n_in,
                              void* d_out, int out_size) {
    const float* x    = (const float*)d_in[0];
    const float* pw   = (const float*)d_in[1];
    const float* pb   = (const float*)d_in[2];
    const float* Kw   = (const float*)d_in[3];
    const float* Rm   = (const float*)d_in[4];
    const float* bias = (const float*)d_in[5];
    float* out = (float*)d_out;

    cudaFuncSetAttribute(gemm_mma_kernel,
                         cudaFuncAttributeMaxDynamicSharedMemorySize, GEMM_SMEM);
    cudaFuncSetAttribute(rnn_tc_kernel,
                         cudaFuncAttributeMaxDynamicSharedMemorySize, RNN_SMEM);

    init_kernel<<<(BB * UU) / 256, 256>>>();
    prep_kernel<<<2048, 256>>>(Kw, Rm);
    conv_kernel<<<dim3(16, BB, 4), 256>>>(x, pw, pb);
    gemm_mma_kernel<<<dim3(UU / 128, MTOT / 128), 256, GEMM_SMEM>>>(bias, out);
    rnn_tc_kernel<<<dim3(16, 16), 256, RNN_SMEM>>>(out);
}